// round 2
// baseline (speedup 1.0000x reference)
#include <cuda_runtime.h>
#include <math.h>
#include <stddef.h>

// Problem constants
#define NMESH 10242
#define NGRID 65160
#define NEDGES 195480
#define DDIM 512
#define NOUT 471

// ---------------------------------------------------------------------------
// Scratch (device globals — no dynamic allocation allowed)
// ---------------------------------------------------------------------------
__device__ float g_e0[(size_t)NEDGES * DDIM];     // edge embedding (400 MB)
__device__ float g_h[(size_t)NEDGES * DDIM];      // generic hidden buffer (400 MB)
__device__ float g_agg[(size_t)NGRID * DDIM];     // segment-sum accumulator
__device__ float g_gridnew[(size_t)NGRID * DDIM]; // updated grid features
__device__ float g_w1pad[DDIM * DDIM];            // out_w1 padded 471 -> 512

// ---------------------------------------------------------------------------
// Small elementwise kernels
// ---------------------------------------------------------------------------
__device__ __forceinline__ float silu_f(float v) {
    return v / (1.0f + expf(-v));
}

// h0[r,c] = silu( sum_j attrs[r,j]*w0[j,c] + b0[c] ),  attrs: [E,4], w0: [4,512]
__global__ void emb_l1_kernel(const float* __restrict__ attrs,
                              const float* __restrict__ w0,
                              const float* __restrict__ b0,
                              float* __restrict__ h0) {
    size_t idx = (size_t)blockIdx.x * blockDim.x + threadIdx.x;
    if (idx >= (size_t)NEDGES * DDIM) return;
    int r = (int)(idx >> 9);
    int c = (int)(idx & 511);
    float v = b0[c];
#pragma unroll
    for (int j = 0; j < 4; j++)
        v = fmaf(attrs[r * 4 + j], w0[j * DDIM + c], v);
    h0[idx] = silu_f(v);
}

__global__ void zero_kernel(float4* __restrict__ p, size_t n4) {
    size_t i = (size_t)blockIdx.x * blockDim.x + threadIdx.x;
    if (i < n4) p[i] = make_float4(0.f, 0.f, 0.f, 0.f);
}

// pad [512,471] -> [512,512] (zero fill)
__global__ void pad_w1_kernel(const float* __restrict__ w, float* __restrict__ wp) {
    int idx = blockIdx.x * blockDim.x + threadIdx.x;
    if (idx >= DDIM * DDIM) return;
    int r = idx >> 9;
    int c = idx & 511;
    wp[idx] = (c < NOUT) ? w[r * NOUT + c] : 0.f;
}

// ---------------------------------------------------------------------------
// Generic fused SGEMM: C[M,N] = epilogue( A[M,K] @ B[K,N] + bias )
//   GM = 0: A direct (row-major, stride lda)
//   GM = 1: A row r = concat( mesh[src[r]], grid[dst[r]], e0[r] )   (K = 1536)
//   GM = 2: A row r = concat( grid[r], agg[r] )                     (K = 1024)
//   ACT : apply silu
//   RES : add resid[r*512 + n]
//   SCAT: atomicAdd into gagg[dst[r]*512 + n] instead of storing C
// BM=BN=128, BK=8, 256 threads, 8x8 per-thread tiles.
// ---------------------------------------------------------------------------
#define BM 128
#define BN 128
#define BK 8

template <int GM, bool ACT, bool RES, bool SCAT>
__global__ __launch_bounds__(256) void sgemm_k(
    const float* __restrict__ A, int lda,
    const float* __restrict__ B, int ldb,
    const float* __restrict__ bias,
    const float* __restrict__ resid,
    float* __restrict__ C, int ldc, int Nc,
    const float* __restrict__ gmesh,
    const float* __restrict__ ggrid,
    const float* __restrict__ ge0,
    float* __restrict__ gagg,
    const int* __restrict__ srcIdx,
    const int* __restrict__ dstIdx,
    int M, int K) {
    __shared__ float As[BK][BM + 4];  // +4 pad: conflict-free transpose stores
    __shared__ float Bs[BK][BN];
    __shared__ int sSrc[BM];
    __shared__ int sDst[BM];

    const int tid = threadIdx.x;
    const int bm = blockIdx.y * BM;
    const int bn = blockIdx.x * BN;

    if (GM == 1) {
        for (int i = tid; i < BM; i += 256) {
            int r = bm + i;
            sSrc[i] = (r < M) ? srcIdx[r] : 0;
            sDst[i] = (r < M) ? dstIdx[r] : 0;
        }
    } else if (SCAT) {
        for (int i = tid; i < BM; i += 256) {
            int r = bm + i;
            sDst[i] = (r < M) ? dstIdx[r] : 0;
        }
    }
    __syncthreads();

    const int aRow = tid >> 1;          // 0..127
    const int aCol = (tid & 1) * 4;     // 0 or 4
    const int bRow = tid >> 5;          // 0..7
    const int bCol = (tid & 31) * 4;    // 0..124
    const int tRow = (tid >> 4) * 8;    // 0..120
    const int tCol = (tid & 15) * 8;    // 0..120

    auto loadA = [&](int k0) -> float4 {
        int r = bm + aRow;
        if (r >= M) return make_float4(0.f, 0.f, 0.f, 0.f);
        int kk = k0 + aCol;
        const float* p;
        if (GM == 0) {
            p = A + (size_t)r * lda + kk;
        } else if (GM == 1) {
            if (kk < 512)
                p = gmesh + (size_t)sSrc[aRow] * DDIM + kk;
            else if (kk < 1024)
                p = ggrid + (size_t)sDst[aRow] * DDIM + (kk - 512);
            else
                p = ge0 + (size_t)r * DDIM + (kk - 1024);
        } else {
            if (kk < 512)
                p = ggrid + (size_t)r * DDIM + kk;
            else
                p = gagg + (size_t)r * DDIM + (kk - 512);
        }
        return *(const float4*)p;
    };
    auto loadB = [&](int k0) -> float4 {
        return *(const float4*)(B + (size_t)(k0 + bRow) * ldb + bn + bCol);
    };

    float acc[8][8];
#pragma unroll
    for (int i = 0; i < 8; i++)
#pragma unroll
        for (int j = 0; j < 8; j++) acc[i][j] = 0.f;

    float4 av = loadA(0);
    float4 bv = loadB(0);

    for (int k0 = 0; k0 < K; k0 += BK) {
        __syncthreads();
        As[aCol + 0][aRow] = av.x;
        As[aCol + 1][aRow] = av.y;
        As[aCol + 2][aRow] = av.z;
        As[aCol + 3][aRow] = av.w;
        *(float4*)&Bs[bRow][bCol] = bv;
        __syncthreads();
        if (k0 + BK < K) {  // prefetch next tile into registers during compute
            av = loadA(k0 + BK);
            bv = loadB(k0 + BK);
        }
#pragma unroll
        for (int kk = 0; kk < BK; kk++) {
            float a[8], b[8];
            *(float4*)&a[0] = *(const float4*)&As[kk][tRow];
            *(float4*)&a[4] = *(const float4*)&As[kk][tRow + 4];
            *(float4*)&b[0] = *(const float4*)&Bs[kk][tCol];
            *(float4*)&b[4] = *(const float4*)&Bs[kk][tCol + 4];
#pragma unroll
            for (int i = 0; i < 8; i++)
#pragma unroll
                for (int j = 0; j < 8; j++)
                    acc[i][j] = fmaf(a[i], b[j], acc[i][j]);
        }
    }

    // Epilogue
#pragma unroll
    for (int i = 0; i < 8; i++) {
        int r = bm + tRow + i;
        if (r >= M) continue;
#pragma unroll
        for (int j = 0; j < 8; j++) {
            int n = bn + tCol + j;
            if (n >= Nc) continue;  // also guards OOB bias read (Nc=471 case)
            float v = acc[i][j] + bias[n];
            if (ACT) v = silu_f(v);
            if (RES) v += resid[(size_t)r * DDIM + n];
            if (SCAT)
                atomicAdd(&gagg[(size_t)sDst[tRow + i] * DDIM + n], v);
            else
                C[(size_t)r * ldc + n] = v;
        }
    }
}

// ---------------------------------------------------------------------------
// Launch
// ---------------------------------------------------------------------------
extern "C" void kernel_launch(void* const* d_in, const int* in_sizes, int n_in,
                              void* d_out, int out_size) {
    (void)in_sizes; (void)n_in; (void)out_size;

    const float* mesh    = (const float*)d_in[0];
    const float* grid    = (const float*)d_in[1];
    const float* attrs   = (const float*)d_in[2];
    const int*   esrc    = (const int*)d_in[3];
    const int*   edst    = (const int*)d_in[4];
    const float* emb_w0  = (const float*)d_in[5];
    const float* emb_b0  = (const float*)d_in[6];
    const float* emb_w1  = (const float*)d_in[7];
    const float* emb_b1  = (const float*)d_in[8];
    const float* edge_w0 = (const float*)d_in[9];
    const float* edge_b0 = (const float*)d_in[10];
    const float* edge_w1 = (const float*)d_in[11];
    const float* edge_b1 = (const float*)d_in[12];
    const float* node_w0 = (const float*)d_in[13];
    const float* node_b0 = (const float*)d_in[14];
    const float* node_w1 = (const float*)d_in[15];
    const float* node_b1 = (const float*)d_in[16];
    const float* out_w0  = (const float*)d_in[17];
    const float* out_b0  = (const float*)d_in[18];
    const float* out_w1  = (const float*)d_in[19];
    const float* out_b1  = (const float*)d_in[20];
    float* out = (float*)d_out;

    float *pE0, *pH, *pAgg, *pGridNew, *pW1p;
    cudaGetSymbolAddress((void**)&pE0, g_e0);
    cudaGetSymbolAddress((void**)&pH, g_h);
    cudaGetSymbolAddress((void**)&pAgg, g_agg);
    cudaGetSymbolAddress((void**)&pGridNew, g_gridnew);
    cudaGetSymbolAddress((void**)&pW1p, g_w1pad);

    const int E = NEDGES, G = NGRID;
    dim3 gridE(DDIM / BN, (E + BM - 1) / BM);
    dim3 gridG(DDIM / BN, (G + BM - 1) / BM);

    // 1) h = silu(attrs @ emb_w0 + emb_b0)
    {
        size_t tot = (size_t)E * DDIM;
        emb_l1_kernel<<<(unsigned)((tot + 255) / 256), 256>>>(attrs, emb_w0, emb_b0, pH);
    }
    // 2) e0 = h @ emb_w1 + emb_b1
    sgemm_k<0, false, false, false><<<gridE, 256>>>(
        pH, DDIM, emb_w1, DDIM, emb_b1, nullptr, pE0, DDIM, DDIM,
        nullptr, nullptr, nullptr, nullptr, nullptr, nullptr, E, DDIM);
    // 3) h = silu( concat(mesh[src], grid[dst], e0) @ edge_w0 + edge_b0 )
    sgemm_k<1, true, false, false><<<gridE, 256>>>(
        nullptr, 0, edge_w0, DDIM, edge_b0, nullptr, pH, DDIM, DDIM,
        mesh, grid, pE0, nullptr, esrc, edst, E, 3 * DDIM);
    // 4) agg = 0
    {
        size_t n4 = (size_t)G * DDIM / 4;
        zero_kernel<<<(unsigned)((n4 + 255) / 256), 256>>>((float4*)pAgg, n4);
    }
    // 5) scatter: agg[dst] += e0 + h @ edge_w1 + edge_b1   (updated edge never stored)
    sgemm_k<0, false, true, true><<<gridE, 256>>>(
        pH, DDIM, edge_w1, DDIM, edge_b1, pE0, nullptr, DDIM, DDIM,
        nullptr, nullptr, nullptr, pAgg, nullptr, edst, E, DDIM);
    // 6) h = silu( concat(grid, agg) @ node_w0 + node_b0 )
    sgemm_k<2, true, false, false><<<gridG, 256>>>(
        nullptr, 0, node_w0, DDIM, node_b0, nullptr, pH, DDIM, DDIM,
        nullptr, grid, nullptr, pAgg, nullptr, nullptr, G, 2 * DDIM);
    // 7) grid_new = grid + h @ node_w1 + node_b1
    sgemm_k<0, false, true, false><<<gridG, 256>>>(
        pH, DDIM, node_w1, DDIM, node_b1, grid, pGridNew, DDIM, DDIM,
        nullptr, nullptr, nullptr, nullptr, nullptr, nullptr, G, DDIM);
    // 8) h = silu( grid_new @ out_w0 + out_b0 )
    sgemm_k<0, true, false, false><<<gridG, 256>>>(
        pGridNew, DDIM, out_w0, DDIM, out_b0, nullptr, pH, DDIM, DDIM,
        nullptr, nullptr, nullptr, nullptr, nullptr, nullptr, G, DDIM);
    // 9) pad out_w1 [512,471] -> [512,512]
    pad_w1_kernel<<<(DDIM * DDIM + 255) / 256, 256>>>(out_w1, pW1p);
    // 10) out = h @ w1pad + out_b1   (store/bias guard at N=471)
    sgemm_k<0, false, false, false><<<gridG, 256>>>(
        pH, DDIM, pW1p, DDIM, out_b1, nullptr, out, NOUT, NOUT,
        nullptr, nullptr, nullptr, nullptr, nullptr, nullptr, G, DDIM);
}

// round 5
// speedup vs baseline: 2.4693x; 2.4693x over previous
#include <cuda_runtime.h>
#include <cuda_bf16.h>
#include <math.h>
#include <stdint.h>
#include <stddef.h>

#define NMESH 10242
#define NGRID 65160
#define NEDGES 195480
#define DDIM 512
#define NOUT 471

// GEMM tiling: CTA 128x128, K-chunk 32 bf16; 8 warps of 64x32
#define BM 128
#define BN 128
#define BK 32
#define NTHR 256

// Smem: [0,512) sSrc, [512,1024) sDst, buffers at 1024
// buffer: Ahi[128][40bf16] (10240B), Alo +10240, Bhi +20480, Blo +30720
#define SMROW 80              // padded row stride bytes (32 bf16 = 64B data + 16B pad)
#define SM_ALO 10240
#define SM_BHI 20480
#define SM_BLO 30720
#define SM_BUFSZ 40960
#define SM_BUFS 1024
#define SM_TOTAL (SM_BUFS + 2 * SM_BUFSZ)

// ---------------------------------------------------------------------------
// Scratch (device globals — no dynamic allocation allowed)
// ---------------------------------------------------------------------------
__device__ float g_e0[(size_t)NEDGES * DDIM];
__device__ float g_h[(size_t)NEDGES * DDIM];
__device__ float g_agg[(size_t)NGRID * DDIM];
__device__ float g_gridnew[(size_t)NGRID * DDIM];

// Pre-transposed / pre-split weights: [N=512 rows][K] row-major bf16
#define OFF_EMBW1  0u         /* K=512  */
#define OFF_EDGEW0 262144u    /* K=1536 */
#define OFF_EDGEW1 1048576u   /* K=512  */
#define OFF_NODEW0 1310720u   /* K=1024 */
#define OFF_NODEW1 1835008u   /* K=512  */
#define OFF_OUTW0  2097152u   /* K=512  */
#define OFF_OUTW1  2359296u   /* K=512, padded from 471 cols */
#define WT_TOTAL   2621440u
__device__ __nv_bfloat16 g_wThi[WT_TOTAL];
__device__ __nv_bfloat16 g_wTlo[WT_TOTAL];

// ---------------------------------------------------------------------------
// Helpers
// ---------------------------------------------------------------------------
__device__ __forceinline__ uint32_t smem_u32(const void* p) {
    uint32_t a;
    asm("{ .reg .u64 t; cvta.to.shared.u64 t, %1; cvt.u32.u64 %0, t; }"
        : "=r"(a) : "l"(p));
    return a;
}
__device__ __forceinline__ void cpasync16(uint32_t dst, const void* src) {
    asm volatile("cp.async.cg.shared.global [%0], [%1], 16;"
                 :: "r"(dst), "l"(src) : "memory");
}
__device__ __forceinline__ void cp_commit() {
    asm volatile("cp.async.commit_group;" ::: "memory");
}
__device__ __forceinline__ void cp_wait_all() {
    asm volatile("cp.async.wait_group 0;" ::: "memory");
}
__device__ __forceinline__ void ldsm4(uint32_t* r, uint32_t addr) {
    asm volatile("ldmatrix.sync.aligned.m8n8.x4.shared.b16 {%0,%1,%2,%3}, [%4];"
                 : "=r"(r[0]), "=r"(r[1]), "=r"(r[2]), "=r"(r[3]) : "r"(addr));
}
__device__ __forceinline__ void mma_bf16(float* c, const uint32_t* a, const uint32_t* b) {
    asm volatile(
        "mma.sync.aligned.m16n8k16.row.col.f32.bf16.bf16.f32 "
        "{%0,%1,%2,%3}, {%4,%5,%6,%7}, {%8,%9}, {%0,%1,%2,%3};"
        : "+f"(c[0]), "+f"(c[1]), "+f"(c[2]), "+f"(c[3])
        : "r"(a[0]), "r"(a[1]), "r"(a[2]), "r"(a[3]), "r"(b[0]), "r"(b[1]));
}
__device__ __forceinline__ void split4(float4 v, uint2& H, uint2& L) {
    __nv_bfloat16 hx = __float2bfloat16(v.x), hy = __float2bfloat16(v.y);
    __nv_bfloat16 hz = __float2bfloat16(v.z), hw = __float2bfloat16(v.w);
    __nv_bfloat16 lx = __float2bfloat16(v.x - __bfloat162float(hx));
    __nv_bfloat16 ly = __float2bfloat16(v.y - __bfloat162float(hy));
    __nv_bfloat16 lz = __float2bfloat16(v.z - __bfloat162float(hz));
    __nv_bfloat16 lw = __float2bfloat16(v.w - __bfloat162float(hw));
    H.x = (uint32_t)__bfloat16_as_ushort(hx) | ((uint32_t)__bfloat16_as_ushort(hy) << 16);
    H.y = (uint32_t)__bfloat16_as_ushort(hz) | ((uint32_t)__bfloat16_as_ushort(hw) << 16);
    L.x = (uint32_t)__bfloat16_as_ushort(lx) | ((uint32_t)__bfloat16_as_ushort(ly) << 16);
    L.y = (uint32_t)__bfloat16_as_ushort(lz) | ((uint32_t)__bfloat16_as_ushort(lw) << 16);
}
__device__ __forceinline__ float silu_f(float v) {
    return __fdividef(v, 1.0f + __expf(-v));
}

// ---------------------------------------------------------------------------
// Small kernels
// ---------------------------------------------------------------------------
__global__ void emb_l1_kernel(const float* __restrict__ attrs,
                              const float* __restrict__ w0,
                              const float* __restrict__ b0,
                              float* __restrict__ h0) {
    size_t idx = (size_t)blockIdx.x * blockDim.x + threadIdx.x;
    if (idx >= (size_t)NEDGES * DDIM) return;
    int r = (int)(idx >> 9);
    int c = (int)(idx & 511);
    float v = b0[c];
#pragma unroll
    for (int j = 0; j < 4; j++)
        v = fmaf(attrs[r * 4 + j], w0[j * DDIM + c], v);
    h0[idx] = silu_f(v);
}

__global__ void zero_kernel(float4* __restrict__ p, size_t n4) {
    size_t i = (size_t)blockIdx.x * blockDim.x + threadIdx.x;
    if (i < n4) p[i] = make_float4(0.f, 0.f, 0.f, 0.f);
}

// W [K, Nsrc] fp32 row-major  ->  WT_hi/lo [512 rows][K] bf16, rows >= Nsrc zero
__global__ void prep_wT(const float* __restrict__ W, int K, int Nsrc,
                        __nv_bfloat16* __restrict__ hi,
                        __nv_bfloat16* __restrict__ lo) {
    int idx = blockIdx.x * blockDim.x + threadIdx.x;
    if (idx >= 512 * K) return;
    int n = idx / K;
    int k = idx - n * K;
    float v = (n < Nsrc) ? W[(size_t)k * Nsrc + n] : 0.f;
    __nv_bfloat16 h = __float2bfloat16(v);
    hi[idx] = h;
    lo[idx] = __float2bfloat16(v - __bfloat162float(h));
}

// ---------------------------------------------------------------------------
// HMMA fused GEMM: C[M, 512-tiled] = epi( A[M,K] @ WT^T + bias )
//   GM=0: A direct fp32    GM=1: concat(mesh[src],grid[dst],e0) K=1536
//   GM=2: concat(grid, agg) K=1024
//   ACT: silu   RES: += resid   SCAT: atomicAdd into agg[dst[r]]
// bf16 hi/lo split (3 mma passes), fp32 register accumulators.
// ---------------------------------------------------------------------------
template <int GM, bool ACT, bool RES, bool SCAT>
__global__ void __launch_bounds__(NTHR) gemm_mm(
    const float* __restrict__ A, int lda,
    const __nv_bfloat16* __restrict__ BThi,
    const __nv_bfloat16* __restrict__ BTlo,
    const float* __restrict__ bias,
    const float* __restrict__ resid,
    float* __restrict__ C, int ldc, int Nc,
    const float* __restrict__ gmesh,
    const float* __restrict__ ggrid,
    const float* __restrict__ ge0,
    float* __restrict__ gagg,
    const int* __restrict__ srcIdx,
    const int* __restrict__ dstIdx,
    int M, int K) {
    extern __shared__ char sm[];
    const uint32_t smb = smem_u32(sm);
    const int tid = threadIdx.x;
    const int wid = tid >> 5;
    const int lane = tid & 31;
    const int bm = blockIdx.y * BM;
    const int bn = blockIdx.x * BN;
    const int mbase = (wid >> 2) * 64;   // warp m-block (2)
    const int nbase = (wid & 3) * 32;    // warp n-block (4)

    int* sSrc = (int*)(sm);
    int* sDst = (int*)(sm + 512);
    if (GM == 1) {
        for (int i = tid; i < BM; i += NTHR) {
            int r = bm + i;
            sSrc[i] = (r < M) ? srcIdx[r] : 0;
            sDst[i] = (r < M) ? dstIdx[r] : 0;
        }
        __syncthreads();
    }

    // ---- global A fetch into regs (float4 x4 per thread) ----
    auto ldgA = [&](int c, float4* v) {
        int k0 = c * BK;
#pragma unroll
        for (int it = 0; it < 4; ++it) {
            int idx = it * NTHR + tid;
            int row = idx >> 3;
            int kk = k0 + (idx & 7) * 4;
            int r = bm + row;
            v[it] = make_float4(0.f, 0.f, 0.f, 0.f);
            if (r < M) {
                const float* p;
                if (GM == 0) {
                    p = A + (size_t)r * lda + kk;
                } else if (GM == 1) {
                    if (kk < 512)       p = gmesh + (size_t)sSrc[row] * DDIM + kk;
                    else if (kk < 1024) p = ggrid + (size_t)sDst[row] * DDIM + (kk - 512);
                    else                p = ge0 + (size_t)r * DDIM + (kk - 1024);
                } else {
                    if (kk < 512) p = ggrid + (size_t)r * DDIM + kk;
                    else          p = gagg + (size_t)r * DDIM + (kk - 512);
                }
                v[it] = *(const float4*)p;
            }
        }
    };
    // ---- convert + store A hi/lo into buffer ----
    auto stsA = [&](const float4* v, int buf) {
        char* base = sm + SM_BUFS + buf * SM_BUFSZ;
#pragma unroll
        for (int it = 0; it < 4; ++it) {
            int idx = it * NTHR + tid;
            int row = idx >> 3;
            int cg = idx & 7;
            uint2 H, L;
            split4(v[it], H, L);
            uint32_t off = (uint32_t)(row * SMROW + cg * 8);
            *(uint2*)(base + off) = H;
            *(uint2*)(base + SM_ALO + off) = L;
        }
    };
    // ---- cp.async B hi/lo into buffer ----
    auto cpB = [&](int c, int buf) {
        int k0 = c * BK;
        uint32_t Bb = smb + SM_BUFS + buf * SM_BUFSZ + SM_BHI;
#pragma unroll
        for (int it = 0; it < 2; ++it) {
            int idx = it * NTHR + tid;       // 0..511
            int row = idx >> 2;
            int ch = idx & 3;
            uint32_t doff = (uint32_t)(row * SMROW + ch * 16);
            size_t g = (size_t)(bn + row) * K + k0 + ch * 8;
            cpasync16(Bb + doff, BThi + g);
            cpasync16(Bb + (SM_BLO - SM_BHI) + doff, BTlo + g);
        }
        cp_commit();
    };

    float acc[4][4][4];
#pragma unroll
    for (int i = 0; i < 4; i++)
#pragma unroll
        for (int j = 0; j < 4; j++)
#pragma unroll
            for (int e = 0; e < 4; e++) acc[i][j][e] = 0.f;

    const int NC = K / BK;
    float4 areg[4];

    // prologue: chunk 0
    ldgA(0, areg);
    cpB(0, 0);
    stsA(areg, 0);

    for (int c = 0; c < NC; ++c) {
        const int buf = c & 1;
        cp_wait_all();
        __syncthreads();
        if (c + 1 < NC) {
            ldgA(c + 1, areg);
            cpB(c + 1, buf ^ 1);
        }
        // ---- compute chunk from buf ----
        const uint32_t Ab = smb + SM_BUFS + buf * SM_BUFSZ;
        const uint32_t Bb = Ab + SM_BHI;
#pragma unroll
        for (int kh = 0; kh < 2; ++kh) {
            uint32_t bhi[2][4], blo[2][4];
#pragma unroll
            for (int j2 = 0; j2 < 2; ++j2) {
                uint32_t ba = Bb +
                    (uint32_t)((nbase + j2 * 16 + ((lane >> 4) << 3) + (lane & 7)) * SMROW +
                               kh * 32 + ((lane >> 3) & 1) * 16);
                ldsm4(bhi[j2], ba);
                ldsm4(blo[j2], ba + (SM_BLO - SM_BHI));
            }
            uint32_t a[4][4];
            uint32_t aoff[4];
#pragma unroll
            for (int i = 0; i < 4; ++i) {
                aoff[i] = Ab +
                    (uint32_t)((mbase + i * 16 + (lane & 15)) * SMROW +
                               kh * 32 + ((lane >> 4) << 4));
                ldsm4(a[i], aoff[i]);   // A hi
            }
#pragma unroll
            for (int i = 0; i < 4; ++i)
#pragma unroll
                for (int j = 0; j < 4; ++j) {
                    mma_bf16(acc[i][j], a[i], &bhi[j >> 1][(j & 1) * 2]);
                    mma_bf16(acc[i][j], a[i], &blo[j >> 1][(j & 1) * 2]);
                }
#pragma unroll
            for (int i = 0; i < 4; ++i)
                ldsm4(a[i], aoff[i] + SM_ALO);   // A lo
#pragma unroll
            for (int i = 0; i < 4; ++i)
#pragma unroll
                for (int j = 0; j < 4; ++j)
                    mma_bf16(acc[i][j], a[i], &bhi[j >> 1][(j & 1) * 2]);
        }
        if (c + 1 < NC) stsA(areg, buf ^ 1);
    }

    // ---- epilogue: registers -> global ----
    const int gid = lane >> 2, tig = lane & 3;
#pragma unroll
    for (int i = 0; i < 4; ++i) {
        int r0 = bm + mbase + i * 16 + gid;
        int r1 = r0 + 8;
        int d0 = 0, d1 = 0;
        if (SCAT) {
            d0 = (r0 < M) ? dstIdx[r0] : 0;
            d1 = (r1 < M) ? dstIdx[r1] : 0;
        }
#pragma unroll
        for (int j = 0; j < 4; ++j) {
            int n0 = bn + nbase + j * 8 + tig * 2;
#pragma unroll
            for (int e = 0; e < 4; ++e) {
                int r = (e & 2) ? r1 : r0;
                int dd = (e & 2) ? d1 : d0;
                int n = n0 + (e & 1);
                if (r < M && n < Nc) {
                    float v = acc[i][j][e] + bias[n];
                    if (ACT) v = silu_f(v);
                    if (RES) v += resid[(size_t)r * DDIM + n];
                    if (SCAT)
                        atomicAdd(&gagg[(size_t)dd * DDIM + n], v);
                    else
                        C[(size_t)r * ldc + n] = v;
                }
            }
        }
    }
}

// ---------------------------------------------------------------------------
// Launch
// ---------------------------------------------------------------------------
extern "C" void kernel_launch(void* const* d_in, const int* in_sizes, int n_in,
                              void* d_out, int out_size) {
    (void)in_sizes; (void)n_in; (void)out_size;

    const float* mesh    = (const float*)d_in[0];
    const float* grid    = (const float*)d_in[1];
    const float* attrs   = (const float*)d_in[2];
    const int*   esrc    = (const int*)d_in[3];
    const int*   edst    = (const int*)d_in[4];
    const float* emb_w0  = (const float*)d_in[5];
    const float* emb_b0  = (const float*)d_in[6];
    const float* emb_w1  = (const float*)d_in[7];
    const float* emb_b1  = (const float*)d_in[8];
    const float* edge_w0 = (const float*)d_in[9];
    const float* edge_b0 = (const float*)d_in[10];
    const float* edge_w1 = (const float*)d_in[11];
    const float* edge_b1 = (const float*)d_in[12];
    const float* node_w0 = (const float*)d_in[13];
    const float* node_b0 = (const float*)d_in[14];
    const float* node_w1 = (const float*)d_in[15];
    const float* node_b1 = (const float*)d_in[16];
    const float* out_w0  = (const float*)d_in[17];
    const float* out_b0  = (const float*)d_in[18];
    const float* out_w1  = (const float*)d_in[19];
    const float* out_b1  = (const float*)d_in[20];
    float* out = (float*)d_out;

    float *pE0, *pH, *pAgg, *pGridNew;
    __nv_bfloat16 *pWThi, *pWTlo;
    cudaGetSymbolAddress((void**)&pE0, g_e0);
    cudaGetSymbolAddress((void**)&pH, g_h);
    cudaGetSymbolAddress((void**)&pAgg, g_agg);
    cudaGetSymbolAddress((void**)&pGridNew, g_gridnew);
    cudaGetSymbolAddress((void**)&pWThi, g_wThi);
    cudaGetSymbolAddress((void**)&pWTlo, g_wTlo);

    cudaFuncSetAttribute(gemm_mm<0, false, false, false>, cudaFuncAttributeMaxDynamicSharedMemorySize, SM_TOTAL);
    cudaFuncSetAttribute(gemm_mm<1, true, false, false>,  cudaFuncAttributeMaxDynamicSharedMemorySize, SM_TOTAL);
    cudaFuncSetAttribute(gemm_mm<0, false, true, true>,   cudaFuncAttributeMaxDynamicSharedMemorySize, SM_TOTAL);
    cudaFuncSetAttribute(gemm_mm<2, true, false, false>,  cudaFuncAttributeMaxDynamicSharedMemorySize, SM_TOTAL);
    cudaFuncSetAttribute(gemm_mm<0, false, true, false>,  cudaFuncAttributeMaxDynamicSharedMemorySize, SM_TOTAL);
    cudaFuncSetAttribute(gemm_mm<0, true, false, false>,  cudaFuncAttributeMaxDynamicSharedMemorySize, SM_TOTAL);

    const int E = NEDGES, G = NGRID;
    dim3 gridE(4, (E + BM - 1) / BM);
    dim3 gridG(4, (G + BM - 1) / BM);

    // 0) weight transpose + bf16 hi/lo split (tiny)
    prep_wT<<<(512 * 512 + 255) / 256, 256>>>(emb_w1, 512, 512, pWThi + OFF_EMBW1, pWTlo + OFF_EMBW1);
    prep_wT<<<(512 * 1536 + 255) / 256, 256>>>(edge_w0, 1536, 512, pWThi + OFF_EDGEW0, pWTlo + OFF_EDGEW0);
    prep_wT<<<(512 * 512 + 255) / 256, 256>>>(edge_w1, 512, 512, pWThi + OFF_EDGEW1, pWTlo + OFF_EDGEW1);
    prep_wT<<<(512 * 1024 + 255) / 256, 256>>>(node_w0, 1024, 512, pWThi + OFF_NODEW0, pWTlo + OFF_NODEW0);
    prep_wT<<<(512 * 512 + 255) / 256, 256>>>(node_w1, 512, 512, pWThi + OFF_NODEW1, pWTlo + OFF_NODEW1);
    prep_wT<<<(512 * 512 + 255) / 256, 256>>>(out_w0, 512, 512, pWThi + OFF_OUTW0, pWTlo + OFF_OUTW0);
    prep_wT<<<(512 * 512 + 255) / 256, 256>>>(out_w1, 512, NOUT, pWThi + OFF_OUTW1, pWTlo + OFF_OUTW1);

    // 1) h = silu(attrs @ emb_w0 + emb_b0)
    {
        size_t tot = (size_t)E * DDIM;
        emb_l1_kernel<<<(unsigned)((tot + 255) / 256), 256>>>(attrs, emb_w0, emb_b0, pH);
    }
    // 2) e0 = h @ emb_w1 + emb_b1
    gemm_mm<0, false, false, false><<<gridE, NTHR, SM_TOTAL>>>(
        pH, DDIM, pWThi + OFF_EMBW1, pWTlo + OFF_EMBW1, emb_b1, nullptr,
        pE0, DDIM, DDIM, nullptr, nullptr, nullptr, nullptr, nullptr, nullptr, E, DDIM);
    // 3) h = silu( concat(mesh[src], grid[dst], e0) @ edge_w0 + edge_b0 )
    gemm_mm<1, true, false, false><<<gridE, NTHR, SM_TOTAL>>>(
        nullptr, 0, pWThi + OFF_EDGEW0, pWTlo + OFF_EDGEW0, edge_b0, nullptr,
        pH, DDIM, DDIM, mesh, grid, pE0, nullptr, esrc, edst, E, 3 * DDIM);
    // 4) agg = 0
    {
        size_t n4 = (size_t)G * DDIM / 4;
        zero_kernel<<<(unsigned)((n4 + 255) / 256), 256>>>((float4*)pAgg, n4);
    }
    // 5) agg[dst] += e0 + h @ edge_w1 + edge_b1   (updated edge never materialized)
    gemm_mm<0, false, true, true><<<gridE, NTHR, SM_TOTAL>>>(
        pH, DDIM, pWThi + OFF_EDGEW1, pWTlo + OFF_EDGEW1, edge_b1, pE0,
        nullptr, DDIM, DDIM, nullptr, nullptr, nullptr, pAgg, nullptr, edst, E, DDIM);
    // 6) h = silu( concat(grid, agg) @ node_w0 + node_b0 )
    gemm_mm<2, true, false, false><<<gridG, NTHR, SM_TOTAL>>>(
        nullptr, 0, pWThi + OFF_NODEW0, pWTlo + OFF_NODEW0, node_b0, nullptr,
        pH, DDIM, DDIM, nullptr, grid, nullptr, pAgg, nullptr, nullptr, G, 2 * DDIM);
    // 7) grid_new = grid + h @ node_w1 + node_b1
    gemm_mm<0, false, true, false><<<gridG, NTHR, SM_TOTAL>>>(
        pH, DDIM, pWThi + OFF_NODEW1, pWTlo + OFF_NODEW1, node_b1, grid,
        pGridNew, DDIM, DDIM, nullptr, nullptr, nullptr, nullptr, nullptr, nullptr, G, DDIM);
    // 8) h = silu( grid_new @ out_w0 + out_b0 )
    gemm_mm<0, true, false, false><<<gridG, NTHR, SM_TOTAL>>>(
        pGridNew, DDIM, pWThi + OFF_OUTW0, pWTlo + OFF_OUTW0, out_b0, nullptr,
        pH, DDIM, DDIM, nullptr, nullptr, nullptr, nullptr, nullptr, nullptr, G, DDIM);
    // 9) out = h @ out_w1(padded) + out_b1   (store/bias guard at N=471)
    gemm_mm<0, false, false, false><<<gridG, NTHR, SM_TOTAL>>>(
        pH, DDIM, pWThi + OFF_OUTW1, pWTlo + OFF_OUTW1, out_b1, nullptr,
        out, NOUT, NOUT, nullptr, nullptr, nullptr, nullptr, nullptr, nullptr, G, DDIM);
}